// round 15
// baseline (speedup 1.0000x reference)
#include <cuda_runtime.h>
#include <cuda_bf16.h>
#include <math.h>
#include <stdint.h>

// Problem constants
#define BB 2
#define LL 512
#define LM 512
#define DM 256
#define DI 1024
#define DS 128
#define DTR 16
#define NH 8
#define DK 32
#define DFF 1024
#define ROWS (BB*LL)          // 1024
#define XZW (2*DI)            // 2048
#define DBLW (DTR + 2*DS)     // 272
#define NBH (BB*NH)           // 16
#define XP_PAD 320            // padded N stride for x_proj split-K partials

// ---------------- scratch (device globals, no allocation) ----------------
__device__ float g_ln  [ROWS*DM];
__device__ float g_xz  [ROWS*XZW];
__device__ float g_u   [ROWS*DI];
__device__ float g_dbl [ROWS*DBLW];
__device__ float g_dt  [ROWS*DI];
__device__ float g_yact[ROWS*DI];
__device__ float g_h   [ROWS*DM];
__device__ float g_h2  [ROWS*DM];
__device__ float g_q   [ROWS*DM];
__device__ float g_k   [ROWS*DM];
__device__ float g_v   [ROWS*DM];
__device__ float g_att [ROWS*DM];
__device__ float g_ffh [ROWS*DFF];
__device__ float g_part[4*ROWS*XP_PAD];  // split-K partials

// ---------------- LayerNorm: one block (256 thr) per row ----------------
__global__ void ln_kernel(const float* __restrict__ x,
                          const float* __restrict__ a,
                          const float* __restrict__ b,
                          float* __restrict__ out)
{
    int row = blockIdx.x;
    int t = threadIdx.x;
    float v = x[row*DM + t];
    __shared__ float red[DM];
    red[t] = v; __syncthreads();
    #pragma unroll
    for (int s = 128; s > 0; s >>= 1) { if (t < s) red[t] += red[t+s]; __syncthreads(); }
    float mean = red[0] * (1.0f/DM);
    __syncthreads();
    float dx = v - mean;
    red[t] = dx*dx; __syncthreads();
    #pragma unroll
    for (int s = 128; s > 0; s >>= 1) { if (t < s) red[t] += red[t+s]; __syncthreads(); }
    float var = red[0] * (1.0f/(DM-1));
    float stdv = sqrtf(var);
    out[row*DM + t] = a[t]*dx/(stdv + 1e-6f) + b[t];
}

// tf32 round-to-nearest
__device__ __forceinline__ float to_tf32(float x) {
    uint32_t r;
    asm("cvt.rna.tf32.f32 %0, %1;" : "=r"(r) : "f"(x));
    return __uint_as_float(r);
}

// k-pair slot within an 8-k slice: k&7 -> slot
__device__ __forceinline__ int pslot(int j) { return (j & 3) * 2 + (j >> 2); }

#define MMA_TF32(C0,C1,C2,C3,A0,A1,A2,A3,B0,B1) \
    asm volatile( \
        "mma.sync.aligned.m16n8k8.row.col.f32.tf32.tf32.f32 " \
        "{%0,%1,%2,%3}, {%4,%5,%6,%7}, {%8,%9}, {%0,%1,%2,%3};" \
        : "+f"(C0), "+f"(C1), "+f"(C2), "+f"(C3) \
        : "r"(A0), "r"(A1), "r"(A2), "r"(A3), "r"(B0), "r"(B1))

// =======================================================================
//  TF32 tensor-core GEMM body (round-7 proven): k-pair smem layout
//  ACT: 0=none 1=relu 2=softplus
// =======================================================================
template<int BM,int BN,int BK,int WM,int WN,int ACT,bool BIAS,bool RES,bool NG,
         int SPLIT,bool PART>
__device__ __forceinline__
void tgemm_body(const float* __restrict__ A, int lda,
                const float* __restrict__ W,
                const float* __restrict__ bias,
                const float* __restrict__ res,
                float* __restrict__ C, int ldc, int M, int N, int K, int kz)
{
    constexpr int NT  = WM*WN*32;
    constexpr int TM  = BM/WM;
    constexpr int TN  = BN/WN;
    constexpr int MF  = TM/16;
    constexpr int NF  = TN/8;
    constexpr int KF  = BK/4;
    constexpr int NS  = BK/8;
    constexpr int AF4 = BM*KF;
    constexpr int WF4 = BN*KF;
    constexpr int AIT = (AF4+NT-1)/NT;
    constexpr int WIT = (WF4+NT-1)/NT;

    __shared__ float As[2][NS][BM][8];
    __shared__ float Ws[2][NS][BN][8];

    int tid = threadIdx.x;
    int wid = tid >> 5, lane = tid & 31;
    int wm = wid % WM, wn = wid / WM;
    int gid = lane >> 2, tig = lane & 3;
    int m0 = blockIdx.y * BM, n0 = blockIdx.x * BN;

    int kchunk = K / SPLIT;
    int kbase  = (SPLIT > 1) ? kz * kchunk : 0;
    int nkt    = kchunk / BK;
    if (PART) C += (size_t)kz * (size_t)M * ldc;

    float c[MF][NF][4];
    #pragma unroll
    for (int mi = 0; mi < MF; mi++)
        #pragma unroll
        for (int ni = 0; ni < NF; ni++)
            #pragma unroll
            for (int r = 0; r < 4; r++) c[mi][ni][r] = 0.f;

    float4 arg[AIT], wrg[WIT];

    auto fetch = [&](int k0) {
        #pragma unroll
        for (int it = 0; it < AIT; it++) {
            int idx = tid + it * NT;
            if ((AF4 % NT == 0) || idx < AF4) {
                int m = idx / KF, kc = (idx % KF) * 4;
                arg[it] = *(const float4*)&A[(m0 + m) * lda + k0 + kc];
            }
        }
        #pragma unroll
        for (int it = 0; it < WIT; it++) {
            int idx = tid + it * NT;
            if ((WF4 % NT == 0) || idx < WF4) {
                int n = idx / KF, kc = (idx % KF) * 4;
                if (!NG || (n0 + n) < N)
                    wrg[it] = *(const float4*)&W[(n0 + n) * K + k0 + kc];
                else
                    wrg[it] = make_float4(0.f, 0.f, 0.f, 0.f);
            }
        }
    };
    auto stash = [&](int buf) {
        #pragma unroll
        for (int it = 0; it < AIT; it++) {
            int idx = tid + it * NT;
            if ((AF4 % NT == 0) || idx < AF4) {
                int m = idx / KF, kc = (idx % KF) * 4;
                float* dst = &As[buf][kc >> 3][m][(kc & 4) ? 1 : 0];
                dst[0] = to_tf32(arg[it].x);
                dst[2] = to_tf32(arg[it].y);
                dst[4] = to_tf32(arg[it].z);
                dst[6] = to_tf32(arg[it].w);
            }
        }
        #pragma unroll
        for (int it = 0; it < WIT; it++) {
            int idx = tid + it * NT;
            if ((WF4 % NT == 0) || idx < WF4) {
                int n = idx / KF, kc = (idx % KF) * 4;
                float* dst = &Ws[buf][kc >> 3][n][(kc & 4) ? 1 : 0];
                dst[0] = to_tf32(wrg[it].x);
                dst[2] = to_tf32(wrg[it].y);
                dst[4] = to_tf32(wrg[it].z);
                dst[6] = to_tf32(wrg[it].w);
            }
        }
    };

    fetch(kbase);
    stash(0);
    __syncthreads();
    int cur = 0;
    for (int kt = 0; kt < nkt; kt++) {
        if (kt + 1 < nkt) fetch(kbase + (kt + 1) * BK);
        #pragma unroll
        for (int s = 0; s < NS; s++) {
            uint32_t af[MF][4], bf[NF][2];
            #pragma unroll
            for (int mi = 0; mi < MF; mi++) {
                int mb = wm * TM + mi * 16 + gid;
                float2 v0 = *(const float2*)&As[cur][s][mb    ][tig * 2];
                float2 v1 = *(const float2*)&As[cur][s][mb + 8][tig * 2];
                af[mi][0] = __float_as_uint(v0.x);
                af[mi][1] = __float_as_uint(v1.x);
                af[mi][2] = __float_as_uint(v0.y);
                af[mi][3] = __float_as_uint(v1.y);
            }
            #pragma unroll
            for (int ni = 0; ni < NF; ni++) {
                int nb = wn * TN + ni * 8 + gid;
                float2 w0 = *(const float2*)&Ws[cur][s][nb][tig * 2];
                bf[ni][0] = __float_as_uint(w0.x);
                bf[ni][1] = __float_as_uint(w0.y);
            }
            #pragma unroll
            for (int mi = 0; mi < MF; mi++)
                #pragma unroll
                for (int ni = 0; ni < NF; ni++)
                    MMA_TF32(c[mi][ni][0], c[mi][ni][1], c[mi][ni][2], c[mi][ni][3],
                             af[mi][0], af[mi][1], af[mi][2], af[mi][3],
                             bf[ni][0], bf[ni][1]);
        }
        if (kt + 1 < nkt) {
            stash(cur ^ 1);
            __syncthreads();
            cur ^= 1;
        }
    }

    #pragma unroll
    for (int mi = 0; mi < MF; mi++)
        #pragma unroll
        for (int ni = 0; ni < NF; ni++)
            #pragma unroll
            for (int h = 0; h < 2; h++) {
                int gm = m0 + wm * TM + mi * 16 + gid + h * 8;
                int gn = n0 + wn * TN + ni * 8 + tig * 2;
                #pragma unroll
                for (int e = 0; e < 2; e++) {
                    int col = gn + e;
                    float v = c[mi][ni][h * 2 + e];
                    if (PART) {
                        C[(size_t)gm * ldc + col] = v;
                    } else {
                        if (NG && col >= N) continue;
                        if (BIAS) v += bias[col];
                        if (ACT == 1) v = fmaxf(v, 0.f);
                        else if (ACT == 2) v = (v > 20.f) ? v : log1pf(expf(v));
                        if (RES) v += res[(size_t)gm * ldc + col];
                        C[(size_t)gm * ldc + col] = v;
                    }
                }
            }
}

template<int BM,int BN,int BK,int WM,int WN,int ACT,bool BIAS,bool RES,bool NG,
         int SPLIT,bool PART>
__global__ __launch_bounds__(WM*WN*32)
void tgemm(const float* __restrict__ A, int lda,
           const float* __restrict__ W,
           const float* __restrict__ bias,
           const float* __restrict__ res,
           float* __restrict__ C, int ldc, int M, int N, int K)
{
    tgemm_body<BM,BN,BK,WM,WN,ACT,BIAS,RES,NG,SPLIT,PART>
        (A, lda, W, bias, res, C, ldc, M, N, K, blockIdx.z);
}

template<int BM,int BN,int BK,int WM,int WN,int ACT,bool BIAS,bool RES,bool NG,
         int SPLIT = 1, bool PART = false>
static void launch_tgemm(const float* A, int lda, const float* W, const float* bias,
                         const float* res, float* C, int ldc, int M, int N, int K)
{
    dim3 grid((N + BN - 1) / BN, M / BM, SPLIT);
    tgemm<BM,BN,BK,WM,WN,ACT,BIAS,RES,NG,SPLIT,PART>
        <<<grid, WM*WN*32>>>(A, lda, W, bias, res, C, ldc, M, N, K);
}

// ---- fused QKV: grid.z selects (A, W, bias, C) ----
struct QKVArgs {
    const float* A[3];
    const float* W[3];
    const float* B[3];
    float*       C[3];
};

__global__ __launch_bounds__(128)
void tgemm_qkv(QKVArgs q, int lda, int ldc, int M, int N, int K)
{
    int z = blockIdx.z;
    tgemm_body<64,32,32,4,1, 0,true,false,false,1,false>
        (q.A[z], lda, q.W[z], q.B[z], nullptr, q.C[z], ldc, M, N, K, 0);
}

// ---------------- split-K reduce for x_proj (4 partials -> g_dbl) ----------------
__global__ __launch_bounds__(256) void reduce4_x()
{
    int idx = blockIdx.x * 256 + threadIdx.x;
    if (idx >= ROWS * (DBLW/4)) return;
    int gm = idx / (DBLW/4);
    int c4 = (idx % (DBLW/4)) * 4;
    const float* base = g_part + (size_t)gm * XP_PAD + c4;
    float4 s = make_float4(0.f, 0.f, 0.f, 0.f);
    #pragma unroll
    for (int sp = 0; sp < 4; sp++) {
        float4 v = *(const float4*)(base + (size_t)sp * ROWS * XP_PAD);
        s.x += v.x; s.y += v.y; s.z += v.z; s.w += v.w;
    }
    *(float4*)&g_dbl[(size_t)gm * DBLW + c4] = s;
}

// ---- split-K2 reduce with bias+res epilogue (N=DM): C = p0+p1 [+bias] + res
template<bool BIAS>
__global__ __launch_bounds__(256) void reduce2_add(const float* __restrict__ bias,
                                                   const float* __restrict__ res,
                                                   float* __restrict__ C)
{
    int idx = blockIdx.x * 256 + threadIdx.x;    // over ROWS*DM/4
    if (idx >= ROWS * (DM/4)) return;
    int c4 = (idx % (DM/4)) * 4;
    float4 a = *(const float4*)&g_part[idx * 4];
    float4 b = *(const float4*)&g_part[(size_t)ROWS * DM + idx * 4];
    float4 r = *(const float4*)&res[idx * 4];
    a.x += b.x + r.x; a.y += b.y + r.y; a.z += b.z + r.z; a.w += b.w + r.w;
    if (BIAS) {
        float4 bb = *(const float4*)&bias[c4];
        a.x += bb.x; a.y += bb.y; a.z += bb.z; a.w += bb.w;
    }
    *(float4*)&C[idx * 4] = a;
}

// ---------------- causal depthwise conv (k=4) + SiLU ----------------
__global__ void conv_silu_kernel(const float* __restrict__ conv_w,
                                 const float* __restrict__ conv_b)
{
    int idx = blockIdx.x * blockDim.x + threadIdx.x;
    if (idx >= ROWS*DI) return;
    int e = idx % DI;
    int row = idx / DI;
    int l = row % LL, b = row / LL;
    float acc = conv_b[e];
    #pragma unroll
    for (int k = 0; k < 4; k++) {
        int ll = l + k - 3;
        if (ll >= 0) acc = fmaf(g_xz[(b*LL + ll)*XZW + e], conv_w[e*4 + k], acc);
    }
    g_u[idx] = acc / (1.f + __expf(-acc));
}

// ---------------- selective scan: warp per (b,d), unroll-4 reductions ----------------
__global__ void scan_kernel(const float* __restrict__ A_log,
                            const float* __restrict__ Dp)
{
    int wid = (blockIdx.x * blockDim.x + threadIdx.x) >> 5;
    int lane = threadIdx.x & 31;
    int b = wid / DI;
    int d = wid % DI;
    if (b >= BB) return;

    float Av[4], h[4];
    #pragma unroll
    for (int i = 0; i < 4; i++) {
        Av[i] = -expf(A_log[d*DS + lane + 32*i]);
        h[i] = 0.f;
    }
    float Dpd = Dp[d];

    for (int l0 = 0; l0 < LL; l0 += 4) {
        float acc[4], uu[4], zz[4];
        #pragma unroll
        for (int j = 0; j < 4; j++) {
            int row = b*LL + l0 + j;
            float dt = g_dt[row*DI + d];
            uu[j] = g_u[row*DI + d];
            zz[j] = g_xz[row*XZW + DI + d];
            float dtu = dt * uu[j];
            float a = 0.f;
            #pragma unroll
            for (int i = 0; i < 4; i++) {
                float Bm = g_dbl[row*DBLW + DTR + lane + 32*i];
                float Cm = g_dbl[row*DBLW + DTR + DS + lane + 32*i];
                float dA = __expf(dt * Av[i]);
                h[i] = fmaf(dA, h[i], dtu * Bm);
                a = fmaf(h[i], Cm, a);
            }
            acc[j] = a;
        }
        #pragma unroll
        for (int off = 16; off > 0; off >>= 1) {
            #pragma unroll
            for (int j = 0; j < 4; j++)
                acc[j] += __shfl_xor_sync(0xffffffffu, acc[j], off);
        }
        #pragma unroll
        for (int j = 0; j < 4; j++) {
            if (lane == j) {
                int row = b*LL + l0 + j;
                float y = acc[j] + uu[j] * Dpd;
                float sz = zz[j] / (1.f + __expf(-zz[j]));
                g_yact[row*DI + d] = y * sz;
            }
        }
    }
}

// =======================================================================
//  Flash attention: grid (LL/64, NBH) = (8,16), 128 thr (4 warps x 16 q-rows)
//  Online softmax; S and PV via tf32 MMA; k-pair smem layouts throughout.
// =======================================================================
__global__ __launch_bounds__(128) void flash_attn()
{
    int bh = blockIdx.y, b = bh >> 3, h = bh & 7;
    int q0 = blockIdx.x * 64;
    int tid = threadIdx.x;
    int wid = tid >> 5, lane = tid & 31;
    int gid = lane >> 2, tig = lane & 3;
    int mb = wid * 16;

    __shared__ float Qs[4][64][8];   // [d-slice][q][slot]
    __shared__ float Ks[4][64][8];   // [d-slice][kcol][slot]
    __shared__ float Vs[8][32][8];   // [k-slice][d][slot]
    __shared__ float Ps[8][64][8];   // [k-slice][q][slot], per-warp q ranges

    // load Q tile (64 q x 32 d)
    #pragma unroll
    for (int it = 0; it < 4; it++) {
        int f4i = tid + it * 128;
        int r = f4i >> 3, cc = (f4i & 7) * 4;
        float4 qv = *(const float4*)&g_q[(b*LL + q0 + r)*DM + h*DK + cc];
        Qs[(cc+0)>>3][r][pslot((cc+0)&7)] = to_tf32(qv.x);
        Qs[(cc+1)>>3][r][pslot((cc+1)&7)] = to_tf32(qv.y);
        Qs[(cc+2)>>3][r][pslot((cc+2)&7)] = to_tf32(qv.z);
        Qs[(cc+3)>>3][r][pslot((cc+3)&7)] = to_tf32(qv.w);
    }

    float m0 = -1e30f, m1 = -1e30f, l0 = 0.f, l1 = 0.f;
    float o[4][4];
    #pragma unroll
    for (int nd = 0; nd < 4; nd++)
        #pragma unroll
        for (int r = 0; r < 4; r++) o[nd][r] = 0.f;

    const float scale = 0.17677669529663687f;   // 1/sqrt(32)

    for (int kt = 0; kt < LM/64; kt++) {
        int k0 = kt * 64;
        __syncthreads();   // prior iteration done with Ks/Vs
        // load K tile (64 kcol x 32 d) and V tile (64 k x 32 d)
        #pragma unroll
        for (int it = 0; it < 4; it++) {
            int f4i = tid + it * 128;
            int r = f4i >> 3, cc = (f4i & 7) * 4;
            float4 kv = *(const float4*)&g_k[(b*LM + k0 + r)*DM + h*DK + cc];
            Ks[(cc+0)>>3][r][pslot((cc+0)&7)] = to_tf32(kv.x);
            Ks[(cc+1)>>3][r][pslot((cc+1)&7)] = to_tf32(kv.y);
            Ks[(cc+2)>>3][r][pslot((cc+2)&7)] = to_tf32(kv.z);
            Ks[(cc+3)>>3][r][pslot((cc+3)&7)] = to_tf32(kv.w);
            float4 vv = *(const float4*)&g_v[(b*LM + k0 + r)*DM + h*DK + cc];
            int vs = r >> 3, vslot = pslot(r & 7);
            Vs[vs][cc+0][vslot] = to_tf32(vv.x);
            Vs[vs][cc+1][vslot] = to_tf32(vv.y);
            Vs[vs][cc+2][vslot] = to_tf32(vv.z);
            Vs[vs][cc+3][vslot] = to_tf32(vv.w);
        }
        __syncthreads();

        // S = Q @ K^T : warp computes rows [mb, mb+16), all 64 k-cols
        float c[8][4];
        #pragma unroll
        for (int ni = 0; ni < 8; ni++)
            #pragma unroll
            for (int r = 0; r < 4; r++) c[ni][r] = 0.f;
        #pragma unroll
        for (int s = 0; s < 4; s++) {
            uint32_t af[4], bf[8][2];
            float2 a0 = *(const float2*)&Qs[s][mb + gid    ][tig*2];
            float2 a1 = *(const float2*)&Qs[s][mb + gid + 8][tig*2];
            af[0] = __float_as_uint(a0.x); af[1] = __float_as_uint(a1.x);
            af[2] = __float_as_uint(a0.y); af[3] = __float_as_uint(a1.y);
            #pragma unroll
            for (int ni = 0; ni < 8; ni++) {
                float2 w0 = *(const float2*)&Ks[s][ni*8 + gid][tig*2];
                bf[ni][0] = __float_as_uint(w0.x);
                bf[ni][1] = __float_as_uint(w0.y);
            }
            #pragma unroll
            for (int ni = 0; ni < 8; ni++)
                MMA_TF32(c[ni][0], c[ni][1], c[ni][2], c[ni][3],
                         af[0], af[1], af[2], af[3], bf[ni][0], bf[ni][1]);
        }
        #pragma unroll
        for (int ni = 0; ni < 8; ni++)
            #pragma unroll
            for (int r = 0; r < 4; r++) c[ni][r] *= scale;

        // online softmax: rows gid (c[ni][0,1]) and gid+8 (c[ni][2,3])
        float tmax0 = -1e30f, tmax1 = -1e30f;
        #pragma unroll
        for (int ni = 0; ni < 8; ni++) {
            tmax0 = fmaxf(tmax0, fmaxf(c[ni][0], c[ni][1]));
            tmax1 = fmaxf(tmax1, fmaxf(c[ni][2], c[ni][3]));
        }
        #pragma unroll
        for (int off = 1; off <= 2; off <<= 1) {
            tmax0 = fmaxf(tmax0, __shfl_xor_sync(0xffffffffu, tmax0, off));
            tmax1 = fmaxf(tmax1, __shfl_xor_sync(0xffffffffu, tmax1, off));
        }
        float mn0 = fmaxf(m0, tmax0), mn1 = fmaxf(m1, tmax1);
        float al0 = __expf(m0 - mn0), al1 = __expf(m1 - mn1);
        float ts0 = 0.f, ts1 = 0.f;
        #pragma unroll
        for (int ni = 0; ni < 8; ni++) {
            c[ni][0] = __expf(c[ni][0] - mn0);
            c[ni][1] = __expf(c[ni][1] - mn0);
            c[ni][2] = __expf(c[ni][2] - mn1);
            c[ni][3] = __expf(c[ni][3] - mn1);
            ts0 += c[ni][0] + c[ni][1];
            ts1 += c[ni][2] + c[ni][3];
        }
        #pragma unroll
        for (int off = 1; off <= 2; off <<= 1) {
            ts0 += __shfl_xor_sync(0xffffffffu, ts0, off);
            ts1 += __shfl_xor_sync(0xffffffffu, ts1, off);
        }
        l0 = l0 * al0 + ts0;  l1 = l1 * al1 + ts1;
        m0 = mn0;             m1 = mn1;
        #pragma unroll
        for (int nd = 0; nd < 4; nd++) {
            o[nd][0] *= al0; o[nd][1] *= al0;
            o[nd][2] *= al1; o[nd][3] *= al1;
        }

        // store P (exp'd scores) to per-warp smem region, k-pair layout
        #pragma unroll
        for (int ni = 0; ni < 8; ni++) {
            int c0 = ni*8 + tig*2, c1 = c0 + 1;
            Ps[c0 >> 3][mb + gid    ][pslot(c0 & 7)] = c[ni][0];
            Ps[c1 >> 3][mb + gid    ][pslot(c1 & 7)] = c[ni][1];
            Ps[c0 >> 3][mb + gid + 8][pslot(c0 & 7)] = c[ni][2];
            Ps[c1 >> 3][mb + gid + 8][pslot(c1 & 7)] = c[ni][3];
        }
        __syncwarp();

        // O += P @ V
        #pragma unroll
        for (int s = 0; s < 8; s++) {
            uint32_t af[4], bf[4][2];
            float2 a0 = *(const float2*)&Ps[s][mb + gid    ][tig*2];
            float2 a1 = *(const float2*)&Ps[s][mb + gid + 8][tig*2];
            af[0] = __float_as_uint(a0.x); af[1] = __float_as_uint(a1.x);
            af[2] = __float_as_uint(a0.y); af[3] = __float_as_uint(a1.y);
            #pragma unroll
            for (int nd = 0; nd < 4; nd++) {
                float2 w0 = *(const float2*)&Vs[s][nd*8 + gid][tig*2];
                bf[nd][0] = __float_as_uint(w0.x);
                bf[nd][1] = __float_as_uint(w0.y);
            }
            #pragma unroll
            for (int nd = 0; nd < 4; nd++)
                MMA_TF32(o[nd][0], o[nd][1], o[nd][2], o[nd][3],
                         af[0], af[1], af[2], af[3], bf[nd][0], bf[nd][1]);
        }
    }

    float inv0 = 1.f / l0, inv1 = 1.f / l1;
    int r0 = q0 + mb + gid, r1 = r0 + 8;
    #pragma unroll
    for (int nd = 0; nd < 4; nd++) {
        int gd = h*DK + nd*8 + tig*2;
        g_att[(b*LL + r0)*DM + gd + 0] = o[nd][0] * inv0;
        g_att[(b*LL + r0)*DM + gd + 1] = o[nd][1] * inv0;
        g_att[(b*LL + r1)*DM + gd + 0] = o[nd][2] * inv1;
        g_att[(b*LL + r1)*DM + gd + 1] = o[nd][3] * inv1;
    }
}

// ---------------- host orchestration ----------------
extern "C" void kernel_launch(void* const* d_in, const int* in_sizes, int n_in,
                              void* d_out, int out_size)
{
    const float* x          = (const float*)d_in[0];
    const float* memory     = (const float*)d_in[1];
    // d_in[2] src_mask (all true), d_in[3] tgt_mask (unused)
    const float* in_proj_w  = (const float*)d_in[4];
    const float* conv_w     = (const float*)d_in[5];
    const float* conv_b     = (const float*)d_in[6];
    const float* x_proj_w   = (const float*)d_in[7];
    const float* dt_proj_w  = (const float*)d_in[8];
    const float* dt_proj_b  = (const float*)d_in[9];
    const float* A_log      = (const float*)d_in[10];
    const float* Dp         = (const float*)d_in[11];
    const float* out_proj_w = (const float*)d_in[12];
    const float* norm1_a    = (const float*)d_in[13];
    const float* norm1_b    = (const float*)d_in[14];
    const float* norm2_a    = (const float*)d_in[15];
    const float* norm2_b    = (const float*)d_in[16];
    const float* norm3_a    = (const float*)d_in[17];
    const float* norm3_b    = (const float*)d_in[18];
    const float* wq_w       = (const float*)d_in[19];
    const float* wq_b       = (const float*)d_in[20];
    const float* wk_w       = (const float*)d_in[21];
    const float* wk_b       = (const float*)d_in[22];
    const float* wv_w       = (const float*)d_in[23];
    const float* wv_b       = (const float*)d_in[24];
    const float* wo_w       = (const float*)d_in[25];
    const float* wo_b       = (const float*)d_in[26];
    const float* w1_w       = (const float*)d_in[27];
    const float* w1_b       = (const float*)d_in[28];
    const float* w2_w       = (const float*)d_in[29];
    const float* w2_b       = (const float*)d_in[30];
    float* out = (float*)d_out;

    float *p_ln, *p_xz, *p_u, *p_dbl, *p_dt, *p_yact, *p_h, *p_h2;
    float *p_q, *p_k, *p_v, *p_att, *p_ffh, *p_part;
    cudaGetSymbolAddress((void**)&p_ln,   g_ln);
    cudaGetSymbolAddress((void**)&p_xz,   g_xz);
    cudaGetSymbolAddress((void**)&p_u,    g_u);
    cudaGetSymbolAddress((void**)&p_dbl,  g_dbl);
    cudaGetSymbolAddress((void**)&p_dt,   g_dt);
    cudaGetSymbolAddress((void**)&p_yact, g_yact);
    cudaGetSymbolAddress((void**)&p_h,    g_h);
    cudaGetSymbolAddress((void**)&p_h2,   g_h2);
    cudaGetSymbolAddress((void**)&p_q,    g_q);
    cudaGetSymbolAddress((void**)&p_k,    g_k);
    cudaGetSymbolAddress((void**)&p_v,    g_v);
    cudaGetSymbolAddress((void**)&p_att,  g_att);
    cudaGetSymbolAddress((void**)&p_ffh,  g_ffh);
    cudaGetSymbolAddress((void**)&p_part, g_part);

    // ---- Mamba block ----  (round-7 proven configs)
    ln_kernel<<<ROWS, DM>>>(x, norm1_a, norm1_b, p_ln);
    // xz = ln1 @ in_proj_w^T  (1024x2048x256): 64x64 -> 512 blocks
    launch_tgemm<64,64,32,2,2, 0,false,false,false>(p_ln, DM, in_proj_w, nullptr, nullptr, p_xz, XZW, ROWS, XZW, DM);
    // u = silu(causal_conv(xi))
    conv_silu_kernel<<<(ROWS*DI+255)/256, 256>>>(conv_w, conv_b);
    // dbl = u @ x_proj_w^T  (1024x272x1024): split-K4, 64x64 -> 320 blocks
    launch_tgemm<64,64,32,2,2, 0,false,false,true, 4,true>(p_u, DI, x_proj_w, nullptr, nullptr, p_part, XP_PAD, ROWS, DBLW, DI);
    reduce4_x<<<(ROWS*(DBLW/4)+255)/256, 256>>>();
    // dt = softplus(dbl[:, :16] @ dt_proj_w^T + b)  (1024x1024x16): 256 blocks
    launch_tgemm<64,64,16,2,2, 2,true,false,false>(p_dbl, DBLW, dt_proj_w, dt_proj_b, nullptr, p_dt, DI, ROWS, DI, DTR);
    // selective scan + (y + u*Dp)*silu(z)
    scan_kernel<<<(BB*DI)/8, 256>>>(A_log, Dp);
    // h = x + yact @ out_proj_w^T  (1024x256x1024): split-K2 64x32 -> 256 blocks
    launch_tgemm<64,32,32,4,1, 0,false,false,false, 2,true>(p_yact, DI, out_proj_w, nullptr, nullptr, p_part, DM, ROWS, DM, DI);
    reduce2_add<false><<<(ROWS*(DM/4)+255)/256, 256>>>(nullptr, x, p_h);

    // ---- Cross attention ----
    ln_kernel<<<ROWS, DM>>>(p_h, norm2_a, norm2_b, p_ln);
    {
        QKVArgs qa;
        qa.A[0] = p_ln;   qa.W[0] = wq_w; qa.B[0] = wq_b; qa.C[0] = p_q;
        qa.A[1] = memory; qa.W[1] = wk_w; qa.B[1] = wk_b; qa.C[1] = p_k;
        qa.A[2] = memory; qa.W[2] = wv_w; qa.B[2] = wv_b; qa.C[2] = p_v;
        dim3 grid(DM/32, ROWS/64, 3);   // 8 x 16 x 3 = 384 blocks
        tgemm_qkv<<<grid, 128>>>(qa, DM, DM, ROWS, DM, DM);
    }
    {
        dim3 fgrid(LL/64, NBH);
        flash_attn<<<fgrid, 128>>>();
    }
    // h2 = h + att @ wo_w^T + wo_b  (1024x256x256): 64x32 -> 128 blocks
    launch_tgemm<64,32,32,4,1, 0,true,true,false>(p_att, DM, wo_w, wo_b, p_h, p_h2, DM, ROWS, DM, DM);

    // ---- FFN ----
    ln_kernel<<<ROWS, DM>>>(p_h2, norm3_a, norm3_b, p_ln);
    // FF1 (1024x1024x256): 64x64 -> 256 blocks
    launch_tgemm<64,64,32,2,2, 1,true,false,false>(p_ln, DM, w1_w, w1_b, nullptr, p_ffh, DFF, ROWS, DFF, DM);
    // FF2 (1024x256x1024): split-K2 64x32 -> 256 blocks
    launch_tgemm<64,32,32,4,1, 0,false,false,false, 2,true>(p_ffh, DFF, w2_w, w2_b, nullptr, p_part, DM, ROWS, DM, DFF);
    reduce2_add<true><<<(ROWS*(DM/4)+255)/256, 256>>>(w2_b, p_h2, out);
}

// round 16
// speedup vs baseline: 1.0507x; 1.0507x over previous
#include <cuda_runtime.h>
#include <cuda_bf16.h>
#include <math.h>
#include <stdint.h>

// Problem constants
#define BB 2
#define LL 512
#define LM 512
#define DM 256
#define DI 1024
#define DS 128
#define DTR 16
#define NH 8
#define DK 32
#define DFF 1024
#define ROWS (BB*LL)          // 1024
#define XZW (2*DI)            // 2048
#define DBLW (DTR + 2*DS)     // 272
#define NBH (BB*NH)           // 16
#define XP_PAD 320            // padded N stride for x_proj split-K partials

// ---------------- scratch (device globals, no allocation) ----------------
__device__ float g_ln  [ROWS*DM];
__device__ float g_xz  [ROWS*XZW];
__device__ float g_u   [ROWS*DI];
__device__ float g_dbl [ROWS*DBLW];
__device__ float g_dt  [ROWS*DI];
__device__ float g_yact[ROWS*DI];
__device__ float g_h   [ROWS*DM];
__device__ float g_h2  [ROWS*DM];
__device__ float g_q   [ROWS*DM];
__device__ float g_k   [ROWS*DM];
__device__ float g_v   [ROWS*DM];
__device__ float g_att [ROWS*DM];
__device__ float g_ffh [ROWS*DFF];
__device__ float g_part[4*ROWS*XP_PAD];  // split-K partials

// ---------------- LayerNorm: one block (256 thr) per row ----------------
__global__ void ln_kernel(const float* __restrict__ x,
                          const float* __restrict__ a,
                          const float* __restrict__ b,
                          float* __restrict__ out)
{
    int row = blockIdx.x;
    int t = threadIdx.x;
    float v = x[row*DM + t];
    __shared__ float red[DM];
    red[t] = v; __syncthreads();
    #pragma unroll
    for (int s = 128; s > 0; s >>= 1) { if (t < s) red[t] += red[t+s]; __syncthreads(); }
    float mean = red[0] * (1.0f/DM);
    __syncthreads();
    float dx = v - mean;
    red[t] = dx*dx; __syncthreads();
    #pragma unroll
    for (int s = 128; s > 0; s >>= 1) { if (t < s) red[t] += red[t+s]; __syncthreads(); }
    float var = red[0] * (1.0f/(DM-1));
    float stdv = sqrtf(var);
    out[row*DM + t] = a[t]*dx/(stdv + 1e-6f) + b[t];
}

// tf32 round-to-nearest
__device__ __forceinline__ float to_tf32(float x) {
    uint32_t r;
    asm("cvt.rna.tf32.f32 %0, %1;" : "=r"(r) : "f"(x));
    return __uint_as_float(r);
}

// k-pair slot within an 8-k slice: k&7 -> slot
__device__ __forceinline__ int pslot(int j) { return (j & 3) * 2 + (j >> 2); }

#define MMA_TF32(C0,C1,C2,C3,A0,A1,A2,A3,B0,B1) \
    asm volatile( \
        "mma.sync.aligned.m16n8k8.row.col.f32.tf32.tf32.f32 " \
        "{%0,%1,%2,%3}, {%4,%5,%6,%7}, {%8,%9}, {%0,%1,%2,%3};" \
        : "+f"(C0), "+f"(C1), "+f"(C2), "+f"(C3) \
        : "r"(A0), "r"(A1), "r"(A2), "r"(A3), "r"(B0), "r"(B1))

// =======================================================================
//  TF32 tensor-core GEMM body (round-7 proven): k-pair smem layout
//  ACT: 0=none 1=relu 2=softplus
// =======================================================================
template<int BM,int BN,int BK,int WM,int WN,int ACT,bool BIAS,bool RES,bool NG,
         int SPLIT,bool PART>
__device__ __forceinline__
void tgemm_body(const float* __restrict__ A, int lda,
                const float* __restrict__ W,
                const float* __restrict__ bias,
                const float* __restrict__ res,
                float* __restrict__ C, int ldc, int M, int N, int K, int kz)
{
    constexpr int NT  = WM*WN*32;
    constexpr int TM  = BM/WM;
    constexpr int TN  = BN/WN;
    constexpr int MF  = TM/16;
    constexpr int NF  = TN/8;
    constexpr int KF  = BK/4;
    constexpr int NS  = BK/8;
    constexpr int AF4 = BM*KF;
    constexpr int WF4 = BN*KF;
    constexpr int AIT = (AF4+NT-1)/NT;
    constexpr int WIT = (WF4+NT-1)/NT;

    __shared__ float As[2][NS][BM][8];
    __shared__ float Ws[2][NS][BN][8];

    int tid = threadIdx.x;
    int wid = tid >> 5, lane = tid & 31;
    int wm = wid % WM, wn = wid / WM;
    int gid = lane >> 2, tig = lane & 3;
    int m0 = blockIdx.y * BM, n0 = blockIdx.x * BN;

    int kchunk = K / SPLIT;
    int kbase  = (SPLIT > 1) ? kz * kchunk : 0;
    int nkt    = kchunk / BK;
    if (PART) C += (size_t)kz * (size_t)M * ldc;

    float c[MF][NF][4];
    #pragma unroll
    for (int mi = 0; mi < MF; mi++)
        #pragma unroll
        for (int ni = 0; ni < NF; ni++)
            #pragma unroll
            for (int r = 0; r < 4; r++) c[mi][ni][r] = 0.f;

    float4 arg[AIT], wrg[WIT];

    auto fetch = [&](int k0) {
        #pragma unroll
        for (int it = 0; it < AIT; it++) {
            int idx = tid + it * NT;
            if ((AF4 % NT == 0) || idx < AF4) {
                int m = idx / KF, kc = (idx % KF) * 4;
                arg[it] = *(const float4*)&A[(m0 + m) * lda + k0 + kc];
            }
        }
        #pragma unroll
        for (int it = 0; it < WIT; it++) {
            int idx = tid + it * NT;
            if ((WF4 % NT == 0) || idx < WF4) {
                int n = idx / KF, kc = (idx % KF) * 4;
                if (!NG || (n0 + n) < N)
                    wrg[it] = *(const float4*)&W[(n0 + n) * K + k0 + kc];
                else
                    wrg[it] = make_float4(0.f, 0.f, 0.f, 0.f);
            }
        }
    };
    auto stash = [&](int buf) {
        #pragma unroll
        for (int it = 0; it < AIT; it++) {
            int idx = tid + it * NT;
            if ((AF4 % NT == 0) || idx < AF4) {
                int m = idx / KF, kc = (idx % KF) * 4;
                float* dst = &As[buf][kc >> 3][m][(kc & 4) ? 1 : 0];
                dst[0] = to_tf32(arg[it].x);
                dst[2] = to_tf32(arg[it].y);
                dst[4] = to_tf32(arg[it].z);
                dst[6] = to_tf32(arg[it].w);
            }
        }
        #pragma unroll
        for (int it = 0; it < WIT; it++) {
            int idx = tid + it * NT;
            if ((WF4 % NT == 0) || idx < WF4) {
                int n = idx / KF, kc = (idx % KF) * 4;
                float* dst = &Ws[buf][kc >> 3][n][(kc & 4) ? 1 : 0];
                dst[0] = to_tf32(wrg[it].x);
                dst[2] = to_tf32(wrg[it].y);
                dst[4] = to_tf32(wrg[it].z);
                dst[6] = to_tf32(wrg[it].w);
            }
        }
    };

    fetch(kbase);
    stash(0);
    __syncthreads();
    int cur = 0;
    for (int kt = 0; kt < nkt; kt++) {
        if (kt + 1 < nkt) fetch(kbase + (kt + 1) * BK);
        #pragma unroll
        for (int s = 0; s < NS; s++) {
            uint32_t af[MF][4], bf[NF][2];
            #pragma unroll
            for (int mi = 0; mi < MF; mi++) {
                int mb = wm * TM + mi * 16 + gid;
                float2 v0 = *(const float2*)&As[cur][s][mb    ][tig * 2];
                float2 v1 = *(const float2*)&As[cur][s][mb + 8][tig * 2];
                af[mi][0] = __float_as_uint(v0.x);
                af[mi][1] = __float_as_uint(v1.x);
                af[mi][2] = __float_as_uint(v0.y);
                af[mi][3] = __float_as_uint(v1.y);
            }
            #pragma unroll
            for (int ni = 0; ni < NF; ni++) {
                int nb = wn * TN + ni * 8 + gid;
                float2 w0 = *(const float2*)&Ws[cur][s][nb][tig * 2];
                bf[ni][0] = __float_as_uint(w0.x);
                bf[ni][1] = __float_as_uint(w0.y);
            }
            #pragma unroll
            for (int mi = 0; mi < MF; mi++)
                #pragma unroll
                for (int ni = 0; ni < NF; ni++)
                    MMA_TF32(c[mi][ni][0], c[mi][ni][1], c[mi][ni][2], c[mi][ni][3],
                             af[mi][0], af[mi][1], af[mi][2], af[mi][3],
                             bf[ni][0], bf[ni][1]);
        }
        if (kt + 1 < nkt) {
            stash(cur ^ 1);
            __syncthreads();
            cur ^= 1;
        }
    }

    #pragma unroll
    for (int mi = 0; mi < MF; mi++)
        #pragma unroll
        for (int ni = 0; ni < NF; ni++)
            #pragma unroll
            for (int h = 0; h < 2; h++) {
                int gm = m0 + wm * TM + mi * 16 + gid + h * 8;
                int gn = n0 + wn * TN + ni * 8 + tig * 2;
                #pragma unroll
                for (int e = 0; e < 2; e++) {
                    int col = gn + e;
                    float v = c[mi][ni][h * 2 + e];
                    if (PART) {
                        C[(size_t)gm * ldc + col] = v;
                    } else {
                        if (NG && col >= N) continue;
                        if (BIAS) v += bias[col];
                        if (ACT == 1) v = fmaxf(v, 0.f);
                        else if (ACT == 2) v = (v > 20.f) ? v : log1pf(expf(v));
                        if (RES) v += res[(size_t)gm * ldc + col];
                        C[(size_t)gm * ldc + col] = v;
                    }
                }
            }
}

template<int BM,int BN,int BK,int WM,int WN,int ACT,bool BIAS,bool RES,bool NG,
         int SPLIT,bool PART>
__global__ __launch_bounds__(WM*WN*32)
void tgemm(const float* __restrict__ A, int lda,
           const float* __restrict__ W,
           const float* __restrict__ bias,
           const float* __restrict__ res,
           float* __restrict__ C, int ldc, int M, int N, int K)
{
    tgemm_body<BM,BN,BK,WM,WN,ACT,BIAS,RES,NG,SPLIT,PART>
        (A, lda, W, bias, res, C, ldc, M, N, K, blockIdx.z);
}

template<int BM,int BN,int BK,int WM,int WN,int ACT,bool BIAS,bool RES,bool NG,
         int SPLIT = 1, bool PART = false>
static void launch_tgemm(const float* A, int lda, const float* W, const float* bias,
                         const float* res, float* C, int ldc, int M, int N, int K)
{
    dim3 grid((N + BN - 1) / BN, M / BM, SPLIT);
    tgemm<BM,BN,BK,WM,WN,ACT,BIAS,RES,NG,SPLIT,PART>
        <<<grid, WM*WN*32>>>(A, lda, W, bias, res, C, ldc, M, N, K);
}

// ---- fused QKV: grid.z selects (A, W, bias, C) ----
struct QKVArgs {
    const float* A[3];
    const float* W[3];
    const float* B[3];
    float*       C[3];
};

__global__ __launch_bounds__(128)
void tgemm_qkv(QKVArgs q, int lda, int ldc, int M, int N, int K)
{
    int z = blockIdx.z;
    tgemm_body<64,32,32,4,1, 0,true,false,false,1,false>
        (q.A[z], lda, q.W[z], q.B[z], nullptr, q.C[z], ldc, M, N, K, 0);
}

// ---------------- split-K reduce for x_proj (4 partials -> g_dbl) ----------------
__global__ __launch_bounds__(256) void reduce4_x()
{
    int idx = blockIdx.x * 256 + threadIdx.x;
    if (idx >= ROWS * (DBLW/4)) return;
    int gm = idx / (DBLW/4);
    int c4 = (idx % (DBLW/4)) * 4;
    const float* base = g_part + (size_t)gm * XP_PAD + c4;
    float4 s = make_float4(0.f, 0.f, 0.f, 0.f);
    #pragma unroll
    for (int sp = 0; sp < 4; sp++) {
        float4 v = *(const float4*)(base + (size_t)sp * ROWS * XP_PAD);
        s.x += v.x; s.y += v.y; s.z += v.z; s.w += v.w;
    }
    *(float4*)&g_dbl[(size_t)gm * DBLW + c4] = s;
}

// ---- split-K2 reduce with bias+res epilogue (N=DM): C = p0+p1 [+bias] + res
template<bool BIAS>
__global__ __launch_bounds__(256) void reduce2_add(const float* __restrict__ bias,
                                                   const float* __restrict__ res,
                                                   float* __restrict__ C)
{
    int idx = blockIdx.x * 256 + threadIdx.x;    // over ROWS*DM/4
    if (idx >= ROWS * (DM/4)) return;
    int c4 = (idx % (DM/4)) * 4;
    float4 a = *(const float4*)&g_part[idx * 4];
    float4 b = *(const float4*)&g_part[(size_t)ROWS * DM + idx * 4];
    float4 r = *(const float4*)&res[idx * 4];
    a.x += b.x + r.x; a.y += b.y + r.y; a.z += b.z + r.z; a.w += b.w + r.w;
    if (BIAS) {
        float4 bb = *(const float4*)&bias[c4];
        a.x += bb.x; a.y += bb.y; a.z += bb.z; a.w += bb.w;
    }
    *(float4*)&C[idx * 4] = a;
}

// ---------------- causal depthwise conv (k=4) + SiLU ----------------
__global__ void conv_silu_kernel(const float* __restrict__ conv_w,
                                 const float* __restrict__ conv_b)
{
    int idx = blockIdx.x * blockDim.x + threadIdx.x;
    if (idx >= ROWS*DI) return;
    int e = idx % DI;
    int row = idx / DI;
    int l = row % LL, b = row / LL;
    float acc = conv_b[e];
    #pragma unroll
    for (int k = 0; k < 4; k++) {
        int ll = l + k - 3;
        if (ll >= 0) acc = fmaf(g_xz[(b*LL + ll)*XZW + e], conv_w[e*4 + k], acc);
    }
    g_u[idx] = acc / (1.f + __expf(-acc));
}

// ---------------- selective scan: warp per (b,d) ----------------
// Lane owns states [4*lane, 4*lane+4): Bm/Cm are ONE LDG.128 each per step
// (warp covers a contiguous 512B), vs 8 scalar LDG before. All loads for the
// 4-step batch issued before compute (MLP ~20).
__global__ void scan_kernel(const float* __restrict__ A_log,
                            const float* __restrict__ Dp)
{
    int wid = (blockIdx.x * blockDim.x + threadIdx.x) >> 5;
    int lane = threadIdx.x & 31;
    int b = wid / DI;
    int d = wid % DI;
    if (b >= BB) return;

    float Av[4], h[4];
    #pragma unroll
    for (int i = 0; i < 4; i++) {
        Av[i] = -expf(A_log[d*DS + lane*4 + i]);
        h[i] = 0.f;
    }
    float Dpd = Dp[d];

    for (int l0 = 0; l0 < LL; l0 += 4) {
        float dt4[4], uu[4], zz[4];
        float4 Bm[4], Cm[4];
        // batch all loads for the 4 timesteps
        #pragma unroll
        for (int j = 0; j < 4; j++) {
            int row = b*LL + l0 + j;
            dt4[j] = g_dt[row*DI + d];
            uu[j]  = g_u [row*DI + d];
            zz[j]  = g_xz[row*XZW + DI + d];
            Bm[j] = *(const float4*)&g_dbl[row*DBLW + DTR + lane*4];
            Cm[j] = *(const float4*)&g_dbl[row*DBLW + DTR + DS + lane*4];
        }
        float acc[4];
        #pragma unroll
        for (int j = 0; j < 4; j++) {
            float dt = dt4[j];
            float dtu = dt * uu[j];
            float dA0 = __expf(dt * Av[0]);
            float dA1 = __expf(dt * Av[1]);
            float dA2 = __expf(dt * Av[2]);
            float dA3 = __expf(dt * Av[3]);
            h[0] = fmaf(dA0, h[0], dtu * Bm[j].x);
            h[1] = fmaf(dA1, h[1], dtu * Bm[j].y);
            h[2] = fmaf(dA2, h[2], dtu * Bm[j].z);
            h[3] = fmaf(dA3, h[3], dtu * Bm[j].w);
            float a = 0.f;
            a = fmaf(h[0], Cm[j].x, a);
            a = fmaf(h[1], Cm[j].y, a);
            a = fmaf(h[2], Cm[j].z, a);
            a = fmaf(h[3], Cm[j].w, a);
            acc[j] = a;
        }
        #pragma unroll
        for (int off = 16; off > 0; off >>= 1) {
            #pragma unroll
            for (int j = 0; j < 4; j++)
                acc[j] += __shfl_xor_sync(0xffffffffu, acc[j], off);
        }
        #pragma unroll
        for (int j = 0; j < 4; j++) {
            if (lane == j) {
                int row = b*LL + l0 + j;
                float y = acc[j] + uu[j] * Dpd;
                float sz = zz[j] / (1.f + __expf(-zz[j]));
                g_yact[row*DI + d] = y * sz;
            }
        }
    }
}

// =======================================================================
//  Flash attention: grid (LL/64, NBH) = (8,16), 128 thr (4 warps x 16 q-rows)
//  Online softmax; S and PV via tf32 MMA; k-pair smem layouts throughout.
// =======================================================================
__global__ __launch_bounds__(128) void flash_attn()
{
    int bh = blockIdx.y, b = bh >> 3, h = bh & 7;
    int q0 = blockIdx.x * 64;
    int tid = threadIdx.x;
    int wid = tid >> 5, lane = tid & 31;
    int gid = lane >> 2, tig = lane & 3;
    int mb = wid * 16;

    __shared__ float Qs[4][64][8];   // [d-slice][q][slot]
    __shared__ float Ks[4][64][8];   // [d-slice][kcol][slot]
    __shared__ float Vs[8][32][8];   // [k-slice][d][slot]
    __shared__ float Ps[8][64][8];   // [k-slice][q][slot], per-warp q ranges

    // load Q tile (64 q x 32 d)
    #pragma unroll
    for (int it = 0; it < 4; it++) {
        int f4i = tid + it * 128;
        int r = f4i >> 3, cc = (f4i & 7) * 4;
        float4 qv = *(const float4*)&g_q[(b*LL + q0 + r)*DM + h*DK + cc];
        Qs[(cc+0)>>3][r][pslot((cc+0)&7)] = to_tf32(qv.x);
        Qs[(cc+1)>>3][r][pslot((cc+1)&7)] = to_tf32(qv.y);
        Qs[(cc+2)>>3][r][pslot((cc+2)&7)] = to_tf32(qv.z);
        Qs[(cc+3)>>3][r][pslot((cc+3)&7)] = to_tf32(qv.w);
    }

    float m0 = -1e30f, m1 = -1e30f, l0 = 0.f, l1 = 0.f;
    float o[4][4];
    #pragma unroll
    for (int nd = 0; nd < 4; nd++)
        #pragma unroll
        for (int r = 0; r < 4; r++) o[nd][r] = 0.f;

    const float scale = 0.17677669529663687f;   // 1/sqrt(32)

    for (int kt = 0; kt < LM/64; kt++) {
        int k0 = kt * 64;
        __syncthreads();   // prior iteration done with Ks/Vs
        #pragma unroll
        for (int it = 0; it < 4; it++) {
            int f4i = tid + it * 128;
            int r = f4i >> 3, cc = (f4i & 7) * 4;
            float4 kv = *(const float4*)&g_k[(b*LM + k0 + r)*DM + h*DK + cc];
            Ks[(cc+0)>>3][r][pslot((cc+0)&7)] = to_tf32(kv.x);
            Ks[(cc+1)>>3][r][pslot((cc+1)&7)] = to_tf32(kv.y);
            Ks[(cc+2)>>3][r][pslot((cc+2)&7)] = to_tf32(kv.z);
            Ks[(cc+3)>>3][r][pslot((cc+3)&7)] = to_tf32(kv.w);
            float4 vv = *(const float4*)&g_v[(b*LM + k0 + r)*DM + h*DK + cc];
            int vs = r >> 3, vslot = pslot(r & 7);
            Vs[vs][cc+0][vslot] = to_tf32(vv.x);
            Vs[vs][cc+1][vslot] = to_tf32(vv.y);
            Vs[vs][cc+2][vslot] = to_tf32(vv.z);
            Vs[vs][cc+3][vslot] = to_tf32(vv.w);
        }
        __syncthreads();

        // S = Q @ K^T
        float c[8][4];
        #pragma unroll
        for (int ni = 0; ni < 8; ni++)
            #pragma unroll
            for (int r = 0; r < 4; r++) c[ni][r] = 0.f;
        #pragma unroll
        for (int s = 0; s < 4; s++) {
            uint32_t af[4], bf[8][2];
            float2 a0 = *(const float2*)&Qs[s][mb + gid    ][tig*2];
            float2 a1 = *(const float2*)&Qs[s][mb + gid + 8][tig*2];
            af[0] = __float_as_uint(a0.x); af[1] = __float_as_uint(a1.x);
            af[2] = __float_as_uint(a0.y); af[3] = __float_as_uint(a1.y);
            #pragma unroll
            for (int ni = 0; ni < 8; ni++) {
                float2 w0 = *(const float2*)&Ks[s][ni*8 + gid][tig*2];
                bf[ni][0] = __float_as_uint(w0.x);
                bf[ni][1] = __float_as_uint(w0.y);
            }
            #pragma unroll
            for (int ni = 0; ni < 8; ni++)
                MMA_TF32(c[ni][0], c[ni][1], c[ni][2], c[ni][3],
                         af[0], af[1], af[2], af[3], bf[ni][0], bf[ni][1]);
        }
        #pragma unroll
        for (int ni = 0; ni < 8; ni++)
            #pragma unroll
            for (int r = 0; r < 4; r++) c[ni][r] *= scale;

        // online softmax
        float tmax0 = -1e30f, tmax1 = -1e30f;
        #pragma unroll
        for (int ni = 0; ni < 8; ni++) {
            tmax0 = fmaxf(tmax0, fmaxf(c[ni][0], c[ni][1]));
            tmax1 = fmaxf(tmax1, fmaxf(c[ni][2], c[ni][3]));
        }
        #pragma unroll
        for (int off = 1; off <= 2; off <<= 1) {
            tmax0 = fmaxf(tmax0, __shfl_xor_sync(0xffffffffu, tmax0, off));
            tmax1 = fmaxf(tmax1, __shfl_xor_sync(0xffffffffu, tmax1, off));
        }
        float mn0 = fmaxf(m0, tmax0), mn1 = fmaxf(m1, tmax1);
        float al0 = __expf(m0 - mn0), al1 = __expf(m1 - mn1);
        float ts0 = 0.f, ts1 = 0.f;
        #pragma unroll
        for (int ni = 0; ni < 8; ni++) {
            c[ni][0] = __expf(c[ni][0] - mn0);
            c[ni][1] = __expf(c[ni][1] - mn0);
            c[ni][2] = __expf(c[ni][2] - mn1);
            c[ni][3] = __expf(c[ni][3] - mn1);
            ts0 += c[ni][0] + c[ni][1];
            ts1 += c[ni][2] + c[ni][3];
        }
        #pragma unroll
        for (int off = 1; off <= 2; off <<= 1) {
            ts0 += __shfl_xor_sync(0xffffffffu, ts0, off);
            ts1 += __shfl_xor_sync(0xffffffffu, ts1, off);
        }
        l0 = l0 * al0 + ts0;  l1 = l1 * al1 + ts1;
        m0 = mn0;             m1 = mn1;
        #pragma unroll
        for (int nd = 0; nd < 4; nd++) {
            o[nd][0] *= al0; o[nd][1] *= al0;
            o[nd][2] *= al1; o[nd][3] *= al1;
        }

        // store P to per-warp smem region, k-pair layout
        #pragma unroll
        for (int ni = 0; ni < 8; ni++) {
            int c0 = ni*8 + tig*2, c1 = c0 + 1;
            Ps[c0 >> 3][mb + gid    ][pslot(c0 & 7)] = c[ni][0];
            Ps[c1 >> 3][mb + gid    ][pslot(c1 & 7)] = c[ni][1];
            Ps[c0 >> 3][mb + gid + 8][pslot(c0 & 7)] = c[ni][2];
            Ps[c1 >> 3][mb + gid + 8][pslot(c1 & 7)] = c[ni][3];
        }
        __syncwarp();

        // O += P @ V
        #pragma unroll
        for (int s = 0; s < 8; s++) {
            uint32_t af[4], bf[4][2];
            float2 a0 = *(const float2*)&Ps[s][mb + gid    ][tig*2];
            float2 a1 = *(const float2*)&Ps[s][mb + gid + 8][tig*2];
            af[0] = __float_as_uint(a0.x); af[1] = __float_as_uint(a1.x);
            af[2] = __float_as_uint(a0.y); af[3] = __float_as_uint(a1.y);
            #pragma unroll
            for (int nd = 0; nd < 4; nd++) {
                float2 w0 = *(const float2*)&Vs[s][nd*8 + gid][tig*2];
                bf[nd][0] = __float_as_uint(w0.x);
                bf[nd][1] = __float_as_uint(w0.y);
            }
            #pragma unroll
            for (int nd = 0; nd < 4; nd++)
                MMA_TF32(o[nd][0], o[nd][1], o[nd][2], o[nd][3],
                         af[0], af[1], af[2], af[3], bf[nd][0], bf[nd][1]);
        }
    }

    float inv0 = 1.f / l0, inv1 = 1.f / l1;
    int r0 = q0 + mb + gid, r1 = r0 + 8;
    #pragma unroll
    for (int nd = 0; nd < 4; nd++) {
        int gd = h*DK + nd*8 + tig*2;
        g_att[(b*LL + r0)*DM + gd + 0] = o[nd][0] * inv0;
        g_att[(b*LL + r0)*DM + gd + 1] = o[nd][1] * inv0;
        g_att[(b*LL + r1)*DM + gd + 0] = o[nd][2] * inv1;
        g_att[(b*LL + r1)*DM + gd + 1] = o[nd][3] * inv1;
    }
}

// ---------------- host orchestration ----------------
extern "C" void kernel_launch(void* const* d_in, const int* in_sizes, int n_in,
                              void* d_out, int out_size)
{
    const float* x          = (const float*)d_in[0];
    const float* memory     = (const float*)d_in[1];
    // d_in[2] src_mask (all true), d_in[3] tgt_mask (unused)
    const float* in_proj_w  = (const float*)d_in[4];
    const float* conv_w     = (const float*)d_in[5];
    const float* conv_b     = (const float*)d_in[6];
    const float* x_proj_w   = (const float*)d_in[7];
    const float* dt_proj_w  = (const float*)d_in[8];
    const float* dt_proj_b  = (const float*)d_in[9];
    const float* A_log      = (const float*)d_in[10];
    const float* Dp         = (const float*)d_in[11];
    const float* out_proj_w = (const float*)d_in[12];
    const float* norm1_a    = (const float*)d_in[13];
    const float* norm1_b    = (const float*)d_in[14];
    const float* norm2_a    = (const float*)d_in[15];
    const float* norm2_b    = (const float*)d_in[16];
    const float* norm3_a    = (const float*)d_in[17];
    const float* norm3_b    = (const float*)d_in[18];
    const float* wq_w       = (const float*)d_in[19];
    const float* wq_b       = (const float*)d_in[20];
    const float* wk_w       = (const float*)d_in[21];
    const float* wk_b       = (const float*)d_in[22];
    const float* wv_w       = (const float*)d_in[23];
    const float* wv_b       = (const float*)d_in[24];
    const float* wo_w       = (const float*)d_in[25];
    const float* wo_b       = (const float*)d_in[26];
    const float* w1_w       = (const float*)d_in[27];
    const float* w1_b       = (const float*)d_in[28];
    const float* w2_w       = (const float*)d_in[29];
    const float* w2_b       = (const float*)d_in[30];
    float* out = (float*)d_out;

    float *p_ln, *p_xz, *p_u, *p_dbl, *p_dt, *p_yact, *p_h, *p_h2;
    float *p_q, *p_k, *p_v, *p_att, *p_ffh, *p_part;
    cudaGetSymbolAddress((void**)&p_ln,   g_ln);
    cudaGetSymbolAddress((void**)&p_xz,   g_xz);
    cudaGetSymbolAddress((void**)&p_u,    g_u);
    cudaGetSymbolAddress((void**)&p_dbl,  g_dbl);
    cudaGetSymbolAddress((void**)&p_dt,   g_dt);
    cudaGetSymbolAddress((void**)&p_yact, g_yact);
    cudaGetSymbolAddress((void**)&p_h,    g_h);
    cudaGetSymbolAddress((void**)&p_h2,   g_h2);
    cudaGetSymbolAddress((void**)&p_q,    g_q);
    cudaGetSymbolAddress((void**)&p_k,    g_k);
    cudaGetSymbolAddress((void**)&p_v,    g_v);
    cudaGetSymbolAddress((void**)&p_att,  g_att);
    cudaGetSymbolAddress((void**)&p_ffh,  g_ffh);
    cudaGetSymbolAddress((void**)&p_part, g_part);

    // ---- Mamba block ----  (round-7 proven configs)
    ln_kernel<<<ROWS, DM>>>(x, norm1_a, norm1_b, p_ln);
    // xz = ln1 @ in_proj_w^T  (1024x2048x256): 64x64 -> 512 blocks
    launch_tgemm<64,64,32,2,2, 0,false,false,false>(p_ln, DM, in_proj_w, nullptr, nullptr, p_xz, XZW, ROWS, XZW, DM);
    // u = silu(causal_conv(xi))
    conv_silu_kernel<<<(ROWS*DI+255)/256, 256>>>(conv_w, conv_b);
    // dbl = u @ x_proj_w^T  (1024x272x1024): split-K4, 64x64 -> 320 blocks
    launch_tgemm<64,64,32,2,2, 0,false,false,true, 4,true>(p_u, DI, x_proj_w, nullptr, nullptr, p_part, XP_PAD, ROWS, DBLW, DI);
    reduce4_x<<<(ROWS*(DBLW/4)+255)/256, 256>>>();
    // dt = softplus(dbl[:, :16] @ dt_proj_w^T + b)  (1024x1024x16): 256 blocks
    launch_tgemm<64,64,16,2,2, 2,true,false,false>(p_dbl, DBLW, dt_proj_w, dt_proj_b, nullptr, p_dt, DI, ROWS, DI, DTR);
    // selective scan + (y + u*Dp)*silu(z)
    scan_kernel<<<(BB*DI)/8, 256>>>(A_log, Dp);
    // h = x + yact @ out_proj_w^T  (1024x256x1024): split-K2 64x32 -> 256 blocks
    launch_tgemm<64,32,32,4,1, 0,false,false,false, 2,true>(p_yact, DI, out_proj_w, nullptr, nullptr, p_part, DM, ROWS, DM, DI);
    reduce2_add<false><<<(ROWS*(DM/4)+255)/256, 256>>>(nullptr, x, p_h);

    // ---- Cross attention ----
    ln_kernel<<<ROWS, DM>>>(p_h, norm2_a, norm2_b, p_ln);
    {
        QKVArgs qa;
        qa.A[0] = p_ln;   qa.W[0] = wq_w; qa.B[0] = wq_b; qa.C[0] = p_q;
        qa.A[1] = memory; qa.W[1] = wk_w; qa.B[1] = wk_b; qa.C[1] = p_k;
        qa.A[2] = memory; qa.W[2] = wv_w; qa.B[2] = wv_b; qa.C[2] = p_v;
        dim3 grid(DM/32, ROWS/64, 3);   // 8 x 16 x 3 = 384 blocks
        tgemm_qkv<<<grid, 128>>>(qa, DM, DM, ROWS, DM, DM);
    }
    {
        dim3 fgrid(LL/64, NBH);
        flash_attn<<<fgrid, 128>>>();
    }
    // h2 = h + att @ wo_w^T + wo_b  (1024x256x256): 64x32 -> 128 blocks
    launch_tgemm<64,32,32,4,1, 0,true,true,false>(p_att, DM, wo_w, wo_b, p_h, p_h2, DM, ROWS, DM, DM);

    // ---- FFN ----
    ln_kernel<<<ROWS, DM>>>(p_h2, norm3_a, norm3_b, p_ln);
    // FF1 (1024x1024x256): 64x64 -> 256 blocks
    launch_tgemm<64,64,32,2,2, 1,true,false,false>(p_ln, DM, w1_w, w1_b, nullptr, p_ffh, DFF, ROWS, DFF, DM);
    // FF2 (1024x256x1024): split-K2 64x32 -> 256 blocks
    launch_tgemm<64,32,32,4,1, 0,false,false,false, 2,true>(p_ffh, DFF, w2_w, w2_b, nullptr, p_part, DM, ROWS, DM, DFF);
    reduce2_add<true><<<(ROWS*(DM/4)+255)/256, 256>>>(w2_b, p_h2, out);
}

// round 17
// speedup vs baseline: 1.0576x; 1.0066x over previous
#include <cuda_runtime.h>
#include <cuda_bf16.h>
#include <math.h>
#include <stdint.h>

// Problem constants
#define BB 2
#define LL 512
#define LM 512
#define DM 256
#define DI 1024
#define DS 128
#define DTR 16
#define NH 8
#define DK 32
#define DFF 1024
#define ROWS (BB*LL)          // 1024
#define XZW (2*DI)            // 2048
#define DBLW (DTR + 2*DS)     // 272
#define NBH (BB*NH)           // 16
#define XP_PAD 320            // padded N stride for x_proj split-K partials

// ---------------- scratch (device globals, no allocation) ----------------
__device__ float g_ln  [ROWS*DM];
__device__ float g_xz  [ROWS*XZW];
__device__ float g_u   [ROWS*DI];
__device__ float g_dbl [ROWS*DBLW];
__device__ float g_dt  [ROWS*DI];
__device__ float g_yact[ROWS*DI];
__device__ float g_h   [ROWS*DM];
__device__ float g_h2  [ROWS*DM];
__device__ float g_q   [ROWS*DM];
__device__ float g_k   [ROWS*DM];
__device__ float g_v   [ROWS*DM];
__device__ float g_att [ROWS*DM];
__device__ float g_ffh [ROWS*DFF];
__device__ float g_part[8*ROWS*XP_PAD];  // split-K / flash partials (10.5 MB)
__device__ float g_fm  [2*NBH*LL];       // flash row max per split
__device__ float g_fl  [2*NBH*LL];       // flash row sum per split

// ---------------- LayerNorm: one block (256 thr) per row ----------------
__global__ void ln_kernel(const float* __restrict__ x,
                          const float* __restrict__ a,
                          const float* __restrict__ b,
                          float* __restrict__ out)
{
    int row = blockIdx.x;
    int t = threadIdx.x;
    float v = x[row*DM + t];
    __shared__ float red[DM];
    red[t] = v; __syncthreads();
    #pragma unroll
    for (int s = 128; s > 0; s >>= 1) { if (t < s) red[t] += red[t+s]; __syncthreads(); }
    float mean = red[0] * (1.0f/DM);
    __syncthreads();
    float dx = v - mean;
    red[t] = dx*dx; __syncthreads();
    #pragma unroll
    for (int s = 128; s > 0; s >>= 1) { if (t < s) red[t] += red[t+s]; __syncthreads(); }
    float var = red[0] * (1.0f/(DM-1));
    float stdv = sqrtf(var);
    out[row*DM + t] = a[t]*dx/(stdv + 1e-6f) + b[t];
}

// ---- fused: h = p0 + p1 [+ bias] + res ; ln_out = LN(h) ----
template<bool BIAS>
__global__ void reduce_ln(const float* __restrict__ bias,
                          const float* __restrict__ res,
                          const float* __restrict__ a,
                          const float* __restrict__ bvec,
                          float* __restrict__ hout,
                          float* __restrict__ lnout)
{
    int row = blockIdx.x;
    int t = threadIdx.x;
    float v = g_part[(size_t)row*DM + t]
            + g_part[(size_t)ROWS*DM + (size_t)row*DM + t]
            + res[row*DM + t];
    if (BIAS) v += bias[t];
    hout[row*DM + t] = v;
    __shared__ float red[DM];
    red[t] = v; __syncthreads();
    #pragma unroll
    for (int s = 128; s > 0; s >>= 1) { if (t < s) red[t] += red[t+s]; __syncthreads(); }
    float mean = red[0] * (1.0f/DM);
    __syncthreads();
    float dx = v - mean;
    red[t] = dx*dx; __syncthreads();
    #pragma unroll
    for (int s = 128; s > 0; s >>= 1) { if (t < s) red[t] += red[t+s]; __syncthreads(); }
    float var = red[0] * (1.0f/(DM-1));
    float stdv = sqrtf(var);
    lnout[row*DM + t] = a[t]*dx/(stdv + 1e-6f) + bvec[t];
}

// tf32 round-to-nearest
__device__ __forceinline__ float to_tf32(float x) {
    uint32_t r;
    asm("cvt.rna.tf32.f32 %0, %1;" : "=r"(r) : "f"(x));
    return __uint_as_float(r);
}

// k-pair slot within an 8-k slice: k&7 -> slot
__device__ __forceinline__ int pslot(int j) { return (j & 3) * 2 + (j >> 2); }

#define MMA_TF32(C0,C1,C2,C3,A0,A1,A2,A3,B0,B1) \
    asm volatile( \
        "mma.sync.aligned.m16n8k8.row.col.f32.tf32.tf32.f32 " \
        "{%0,%1,%2,%3}, {%4,%5,%6,%7}, {%8,%9}, {%0,%1,%2,%3};" \
        : "+f"(C0), "+f"(C1), "+f"(C2), "+f"(C3) \
        : "r"(A0), "r"(A1), "r"(A2), "r"(A3), "r"(B0), "r"(B1))

// =======================================================================
//  TF32 tensor-core GEMM body (round-7 proven): k-pair smem layout
//  ACT: 0=none 1=relu 2=softplus
// =======================================================================
template<int BM,int BN,int BK,int WM,int WN,int ACT,bool BIAS,bool RES,bool NG,
         int SPLIT,bool PART>
__device__ __forceinline__
void tgemm_body(const float* __restrict__ A, int lda,
                const float* __restrict__ W,
                const float* __restrict__ bias,
                const float* __restrict__ res,
                float* __restrict__ C, int ldc, int M, int N, int K, int kz)
{
    constexpr int NT  = WM*WN*32;
    constexpr int TM  = BM/WM;
    constexpr int TN  = BN/WN;
    constexpr int MF  = TM/16;
    constexpr int NF  = TN/8;
    constexpr int KF  = BK/4;
    constexpr int NS  = BK/8;
    constexpr int AF4 = BM*KF;
    constexpr int WF4 = BN*KF;
    constexpr int AIT = (AF4+NT-1)/NT;
    constexpr int WIT = (WF4+NT-1)/NT;

    __shared__ float As[2][NS][BM][8];
    __shared__ float Ws[2][NS][BN][8];

    int tid = threadIdx.x;
    int wid = tid >> 5, lane = tid & 31;
    int wm = wid % WM, wn = wid / WM;
    int gid = lane >> 2, tig = lane & 3;
    int m0 = blockIdx.y * BM, n0 = blockIdx.x * BN;

    int kchunk = K / SPLIT;
    int kbase  = (SPLIT > 1) ? kz * kchunk : 0;
    int nkt    = kchunk / BK;
    if (PART) C += (size_t)kz * (size_t)M * ldc;

    float c[MF][NF][4];
    #pragma unroll
    for (int mi = 0; mi < MF; mi++)
        #pragma unroll
        for (int ni = 0; ni < NF; ni++)
            #pragma unroll
            for (int r = 0; r < 4; r++) c[mi][ni][r] = 0.f;

    float4 arg[AIT], wrg[WIT];

    auto fetch = [&](int k0) {
        #pragma unroll
        for (int it = 0; it < AIT; it++) {
            int idx = tid + it * NT;
            if ((AF4 % NT == 0) || idx < AF4) {
                int m = idx / KF, kc = (idx % KF) * 4;
                arg[it] = *(const float4*)&A[(m0 + m) * lda + k0 + kc];
            }
        }
        #pragma unroll
        for (int it = 0; it < WIT; it++) {
            int idx = tid + it * NT;
            if ((WF4 % NT == 0) || idx < WF4) {
                int n = idx / KF, kc = (idx % KF) * 4;
                if (!NG || (n0 + n) < N)
                    wrg[it] = *(const float4*)&W[(n0 + n) * K + k0 + kc];
                else
                    wrg[it] = make_float4(0.f, 0.f, 0.f, 0.f);
            }
        }
    };
    auto stash = [&](int buf) {
        #pragma unroll
        for (int it = 0; it < AIT; it++) {
            int idx = tid + it * NT;
            if ((AF4 % NT == 0) || idx < AF4) {
                int m = idx / KF, kc = (idx % KF) * 4;
                float* dst = &As[buf][kc >> 3][m][(kc & 4) ? 1 : 0];
                dst[0] = to_tf32(arg[it].x);
                dst[2] = to_tf32(arg[it].y);
                dst[4] = to_tf32(arg[it].z);
                dst[6] = to_tf32(arg[it].w);
            }
        }
        #pragma unroll
        for (int it = 0; it < WIT; it++) {
            int idx = tid + it * NT;
            if ((WF4 % NT == 0) || idx < WF4) {
                int n = idx / KF, kc = (idx % KF) * 4;
                float* dst = &Ws[buf][kc >> 3][n][(kc & 4) ? 1 : 0];
                dst[0] = to_tf32(wrg[it].x);
                dst[2] = to_tf32(wrg[it].y);
                dst[4] = to_tf32(wrg[it].z);
                dst[6] = to_tf32(wrg[it].w);
            }
        }
    };

    fetch(kbase);
    stash(0);
    __syncthreads();
    int cur = 0;
    for (int kt = 0; kt < nkt; kt++) {
        if (kt + 1 < nkt) fetch(kbase + (kt + 1) * BK);
        #pragma unroll
        for (int s = 0; s < NS; s++) {
            uint32_t af[MF][4], bf[NF][2];
            #pragma unroll
            for (int mi = 0; mi < MF; mi++) {
                int mb = wm * TM + mi * 16 + gid;
                float2 v0 = *(const float2*)&As[cur][s][mb    ][tig * 2];
                float2 v1 = *(const float2*)&As[cur][s][mb + 8][tig * 2];
                af[mi][0] = __float_as_uint(v0.x);
                af[mi][1] = __float_as_uint(v1.x);
                af[mi][2] = __float_as_uint(v0.y);
                af[mi][3] = __float_as_uint(v1.y);
            }
            #pragma unroll
            for (int ni = 0; ni < NF; ni++) {
                int nb = wn * TN + ni * 8 + gid;
                float2 w0 = *(const float2*)&Ws[cur][s][nb][tig * 2];
                bf[ni][0] = __float_as_uint(w0.x);
                bf[ni][1] = __float_as_uint(w0.y);
            }
            #pragma unroll
            for (int mi = 0; mi < MF; mi++)
                #pragma unroll
                for (int ni = 0; ni < NF; ni++)
                    MMA_TF32(c[mi][ni][0], c[mi][ni][1], c[mi][ni][2], c[mi][ni][3],
                             af[mi][0], af[mi][1], af[mi][2], af[mi][3],
                             bf[ni][0], bf[ni][1]);
        }
        if (kt + 1 < nkt) {
            stash(cur ^ 1);
            __syncthreads();
            cur ^= 1;
        }
    }

    #pragma unroll
    for (int mi = 0; mi < MF; mi++)
        #pragma unroll
        for (int ni = 0; ni < NF; ni++)
            #pragma unroll
            for (int h = 0; h < 2; h++) {
                int gm = m0 + wm * TM + mi * 16 + gid + h * 8;
                int gn = n0 + wn * TN + ni * 8 + tig * 2;
                #pragma unroll
                for (int e = 0; e < 2; e++) {
                    int col = gn + e;
                    float v = c[mi][ni][h * 2 + e];
                    if (PART) {
                        C[(size_t)gm * ldc + col] = v;
                    } else {
                        if (NG && col >= N) continue;
                        if (BIAS) v += bias[col];
                        if (ACT == 1) v = fmaxf(v, 0.f);
                        else if (ACT == 2) v = (v > 20.f) ? v : log1pf(expf(v));
                        if (RES) v += res[(size_t)gm * ldc + col];
                        C[(size_t)gm * ldc + col] = v;
                    }
                }
            }
}

template<int BM,int BN,int BK,int WM,int WN,int ACT,bool BIAS,bool RES,bool NG,
         int SPLIT,bool PART>
__global__ __launch_bounds__(WM*WN*32)
void tgemm(const float* __restrict__ A, int lda,
           const float* __restrict__ W,
           const float* __restrict__ bias,
           const float* __restrict__ res,
           float* __restrict__ C, int ldc, int M, int N, int K)
{
    tgemm_body<BM,BN,BK,WM,WN,ACT,BIAS,RES,NG,SPLIT,PART>
        (A, lda, W, bias, res, C, ldc, M, N, K, blockIdx.z);
}

template<int BM,int BN,int BK,int WM,int WN,int ACT,bool BIAS,bool RES,bool NG,
         int SPLIT = 1, bool PART = false>
static void launch_tgemm(const float* A, int lda, const float* W, const float* bias,
                         const float* res, float* C, int ldc, int M, int N, int K)
{
    dim3 grid((N + BN - 1) / BN, M / BM, SPLIT);
    tgemm<BM,BN,BK,WM,WN,ACT,BIAS,RES,NG,SPLIT,PART>
        <<<grid, WM*WN*32>>>(A, lda, W, bias, res, C, ldc, M, N, K);
}

// ---- fused QKV: grid.z selects (A, W, bias, C) ----
struct QKVArgs {
    const float* A[3];
    const float* W[3];
    const float* B[3];
    float*       C[3];
};

__global__ __launch_bounds__(128)
void tgemm_qkv(QKVArgs q, int lda, int ldc, int M, int N, int K)
{
    int z = blockIdx.z;
    tgemm_body<64,32,32,4,1, 0,true,false,false,1,false>
        (q.A[z], lda, q.W[z], q.B[z], nullptr, q.C[z], ldc, M, N, K, 0);
}

// ---------------- split-K reduce for x_proj (SP partials -> g_dbl) ----------------
template<int SP>
__global__ __launch_bounds__(256) void reduceN_x()
{
    int idx = blockIdx.x * 256 + threadIdx.x;
    if (idx >= ROWS * (DBLW/4)) return;
    int gm = idx / (DBLW/4);
    int c4 = (idx % (DBLW/4)) * 4;
    const float* base = g_part + (size_t)gm * XP_PAD + c4;
    float4 s = make_float4(0.f, 0.f, 0.f, 0.f);
    #pragma unroll
    for (int sp = 0; sp < SP; sp++) {
        float4 v = *(const float4*)(base + (size_t)sp * ROWS * XP_PAD);
        s.x += v.x; s.y += v.y; s.z += v.z; s.w += v.w;
    }
    *(float4*)&g_dbl[(size_t)gm * DBLW + c4] = s;
}

// ---- split-K2 reduce with bias+res epilogue (N=DM): C = p0+p1 [+bias] + res
template<bool BIAS>
__global__ __launch_bounds__(256) void reduce2_add(const float* __restrict__ bias,
                                                   const float* __restrict__ res,
                                                   float* __restrict__ C)
{
    int idx = blockIdx.x * 256 + threadIdx.x;
    if (idx >= ROWS * (DM/4)) return;
    int c4 = (idx % (DM/4)) * 4;
    float4 a = *(const float4*)&g_part[idx * 4];
    float4 b = *(const float4*)&g_part[(size_t)ROWS * DM + idx * 4];
    float4 r = *(const float4*)&res[idx * 4];
    a.x += b.x + r.x; a.y += b.y + r.y; a.z += b.z + r.z; a.w += b.w + r.w;
    if (BIAS) {
        float4 bb = *(const float4*)&bias[c4];
        a.x += bb.x; a.y += bb.y; a.z += bb.z; a.w += bb.w;
    }
    *(float4*)&C[idx * 4] = a;
}

// ---------------- causal depthwise conv (k=4) + SiLU ----------------
__global__ void conv_silu_kernel(const float* __restrict__ conv_w,
                                 const float* __restrict__ conv_b)
{
    int idx = blockIdx.x * blockDim.x + threadIdx.x;
    if (idx >= ROWS*DI) return;
    int e = idx % DI;
    int row = idx / DI;
    int l = row % LL, b = row / LL;
    float acc = conv_b[e];
    #pragma unroll
    for (int k = 0; k < 4; k++) {
        int ll = l + k - 3;
        if (ll >= 0) acc = fmaf(g_xz[(b*LL + ll)*XZW + e], conv_w[e*4 + k], acc);
    }
    g_u[idx] = acc / (1.f + __expf(-acc));
}

// ---------------- selective scan: warp per (b,d), LDG.128 states ----------------
__global__ void scan_kernel(const float* __restrict__ A_log,
                            const float* __restrict__ Dp)
{
    int wid = (blockIdx.x * blockDim.x + threadIdx.x) >> 5;
    int lane = threadIdx.x & 31;
    int b = wid / DI;
    int d = wid % DI;
    if (b >= BB) return;

    float Av[4], h[4];
    #pragma unroll
    for (int i = 0; i < 4; i++) {
        Av[i] = -expf(A_log[d*DS + lane*4 + i]);
        h[i] = 0.f;
    }
    float Dpd = Dp[d];

    for (int l0 = 0; l0 < LL; l0 += 4) {
        float dt4[4], uu[4], zz[4];
        float4 Bm[4], Cm[4];
        #pragma unroll
        for (int j = 0; j < 4; j++) {
            int row = b*LL + l0 + j;
            dt4[j] = g_dt[row*DI + d];
            uu[j]  = g_u [row*DI + d];
            zz[j]  = g_xz[row*XZW + DI + d];
            Bm[j] = *(const float4*)&g_dbl[row*DBLW + DTR + lane*4];
            Cm[j] = *(const float4*)&g_dbl[row*DBLW + DTR + DS + lane*4];
        }
        float acc[4];
        #pragma unroll
        for (int j = 0; j < 4; j++) {
            float dt = dt4[j];
            float dtu = dt * uu[j];
            float dA0 = __expf(dt * Av[0]);
            float dA1 = __expf(dt * Av[1]);
            float dA2 = __expf(dt * Av[2]);
            float dA3 = __expf(dt * Av[3]);
            h[0] = fmaf(dA0, h[0], dtu * Bm[j].x);
            h[1] = fmaf(dA1, h[1], dtu * Bm[j].y);
            h[2] = fmaf(dA2, h[2], dtu * Bm[j].z);
            h[3] = fmaf(dA3, h[3], dtu * Bm[j].w);
            float a = 0.f;
            a = fmaf(h[0], Cm[j].x, a);
            a = fmaf(h[1], Cm[j].y, a);
            a = fmaf(h[2], Cm[j].z, a);
            a = fmaf(h[3], Cm[j].w, a);
            acc[j] = a;
        }
        #pragma unroll
        for (int off = 16; off > 0; off >>= 1) {
            #pragma unroll
            for (int j = 0; j < 4; j++)
                acc[j] += __shfl_xor_sync(0xffffffffu, acc[j], off);
        }
        #pragma unroll
        for (int j = 0; j < 4; j++) {
            if (lane == j) {
                int row = b*LL + l0 + j;
                float y = acc[j] + uu[j] * Dpd;
                float sz = zz[j] / (1.f + __expf(-zz[j]));
                g_yact[row*DI + d] = y * sz;
            }
        }
    }
}

// =======================================================================
//  Flash attention, KV-split-2: grid (LL/64, NBH, 2), 128 thr.
//  Each block: 64 q-rows x 256 kv. Writes UNNORMALIZED O + (m, l) per row.
// =======================================================================
__global__ __launch_bounds__(128) void flash_attn()
{
    int bh = blockIdx.y, b = bh >> 3, h = bh & 7;
    int q0 = blockIdx.x * 64;
    int z  = blockIdx.z;
    int tid = threadIdx.x;
    int wid = tid >> 5, lane = tid & 31;
    int gid = lane >> 2, tig = lane & 3;
    int mb = wid * 16;

    __shared__ float Qs[4][64][8];
    __shared__ float Ks[4][64][8];
    __shared__ float Vs[8][32][8];
    __shared__ float Ps[8][64][8];

    #pragma unroll
    for (int it = 0; it < 4; it++) {
        int f4i = tid + it * 128;
        int r = f4i >> 3, cc = (f4i & 7) * 4;
        float4 qv = *(const float4*)&g_q[(b*LL + q0 + r)*DM + h*DK + cc];
        Qs[(cc+0)>>3][r][pslot((cc+0)&7)] = to_tf32(qv.x);
        Qs[(cc+1)>>3][r][pslot((cc+1)&7)] = to_tf32(qv.y);
        Qs[(cc+2)>>3][r][pslot((cc+2)&7)] = to_tf32(qv.z);
        Qs[(cc+3)>>3][r][pslot((cc+3)&7)] = to_tf32(qv.w);
    }

    float m0 = -1e30f, m1 = -1e30f, l0 = 0.f, l1 = 0.f;
    float o[4][4];
    #pragma unroll
    for (int nd = 0; nd < 4; nd++)
        #pragma unroll
        for (int r = 0; r < 4; r++) o[nd][r] = 0.f;

    const float scale = 0.17677669529663687f;   // 1/sqrt(32)

    for (int kt = 0; kt < 4; kt++) {
        int k0 = z * 256 + kt * 64;
        __syncthreads();
        #pragma unroll
        for (int it = 0; it < 4; it++) {
            int f4i = tid + it * 128;
            int r = f4i >> 3, cc = (f4i & 7) * 4;
            float4 kv = *(const float4*)&g_k[(b*LM + k0 + r)*DM + h*DK + cc];
            Ks[(cc+0)>>3][r][pslot((cc+0)&7)] = to_tf32(kv.x);
            Ks[(cc+1)>>3][r][pslot((cc+1)&7)] = to_tf32(kv.y);
            Ks[(cc+2)>>3][r][pslot((cc+2)&7)] = to_tf32(kv.z);
            Ks[(cc+3)>>3][r][pslot((cc+3)&7)] = to_tf32(kv.w);
            float4 vv = *(const float4*)&g_v[(b*LM + k0 + r)*DM + h*DK + cc];
            int vs = r >> 3, vslot = pslot(r & 7);
            Vs[vs][cc+0][vslot] = to_tf32(vv.x);
            Vs[vs][cc+1][vslot] = to_tf32(vv.y);
            Vs[vs][cc+2][vslot] = to_tf32(vv.z);
            Vs[vs][cc+3][vslot] = to_tf32(vv.w);
        }
        __syncthreads();

        float c[8][4];
        #pragma unroll
        for (int ni = 0; ni < 8; ni++)
            #pragma unroll
            for (int r = 0; r < 4; r++) c[ni][r] = 0.f;
        #pragma unroll
        for (int s = 0; s < 4; s++) {
            uint32_t af[4], bf[8][2];
            float2 a0 = *(const float2*)&Qs[s][mb + gid    ][tig*2];
            float2 a1 = *(const float2*)&Qs[s][mb + gid + 8][tig*2];
            af[0] = __float_as_uint(a0.x); af[1] = __float_as_uint(a1.x);
            af[2] = __float_as_uint(a0.y); af[3] = __float_as_uint(a1.y);
            #pragma unroll
            for (int ni = 0; ni < 8; ni++) {
                float2 w0 = *(const float2*)&Ks[s][ni*8 + gid][tig*2];
                bf[ni][0] = __float_as_uint(w0.x);
                bf[ni][1] = __float_as_uint(w0.y);
            }
            #pragma unroll
            for (int ni = 0; ni < 8; ni++)
                MMA_TF32(c[ni][0], c[ni][1], c[ni][2], c[ni][3],
                         af[0], af[1], af[2], af[3], bf[ni][0], bf[ni][1]);
        }
        #pragma unroll
        for (int ni = 0; ni < 8; ni++)
            #pragma unroll
            for (int r = 0; r < 4; r++) c[ni][r] *= scale;

        float tmax0 = -1e30f, tmax1 = -1e30f;
        #pragma unroll
        for (int ni = 0; ni < 8; ni++) {
            tmax0 = fmaxf(tmax0, fmaxf(c[ni][0], c[ni][1]));
            tmax1 = fmaxf(tmax1, fmaxf(c[ni][2], c[ni][3]));
        }
        #pragma unroll
        for (int off = 1; off <= 2; off <<= 1) {
            tmax0 = fmaxf(tmax0, __shfl_xor_sync(0xffffffffu, tmax0, off));
            tmax1 = fmaxf(tmax1, __shfl_xor_sync(0xffffffffu, tmax1, off));
        }
        float mn0 = fmaxf(m0, tmax0), mn1 = fmaxf(m1, tmax1);
        float al0 = __expf(m0 - mn0), al1 = __expf(m1 - mn1);
        float ts0 = 0.f, ts1 = 0.f;
        #pragma unroll
        for (int ni = 0; ni < 8; ni++) {
            c[ni][0] = __expf(c[ni][0] - mn0);
            c[ni][1] = __expf(c[ni][1] - mn0);
            c[ni][2] = __expf(c[ni][2] - mn1);
            c[ni][3] = __expf(c[ni][3] - mn1);
            ts0 += c[ni][0] + c[ni][1];
            ts1 += c[ni][2] + c[ni][3];
        }
        #pragma unroll
        for (int off = 1; off <= 2; off <<= 1) {
            ts0 += __shfl_xor_sync(0xffffffffu, ts0, off);
            ts1 += __shfl_xor_sync(0xffffffffu, ts1, off);
        }
        l0 = l0 * al0 + ts0;  l1 = l1 * al1 + ts1;
        m0 = mn0;             m1 = mn1;
        #pragma unroll
        for (int nd = 0; nd < 4; nd++) {
            o[nd][0] *= al0; o[nd][1] *= al0;
            o[nd][2] *= al1; o[nd][3] *= al1;
        }

        #pragma unroll
        for (int ni = 0; ni < 8; ni++) {
            int c0 = ni*8 + tig*2, c1 = c0 + 1;
            Ps[c0 >> 3][mb + gid    ][pslot(c0 & 7)] = c[ni][0];
            Ps[c1 >> 3][mb + gid    ][pslot(c1 & 7)] = c[ni][1];
            Ps[c0 >> 3][mb + gid + 8][pslot(c0 & 7)] = c[ni][2];
            Ps[c1 >> 3][mb + gid + 8][pslot(c1 & 7)] = c[ni][3];
        }
        __syncwarp();

        #pragma unroll
        for (int s = 0; s < 8; s++) {
            uint32_t af[4], bf[4][2];
            float2 a0 = *(const float2*)&Ps[s][mb + gid    ][tig*2];
            float2 a1 = *(const float2*)&Ps[s][mb + gid + 8][tig*2];
            af[0] = __float_as_uint(a0.x); af[1] = __float_as_uint(a1.x);
            af[2] = __float_as_uint(a0.y); af[3] = __float_as_uint(a1.y);
            #pragma unroll
            for (int nd = 0; nd < 4; nd++) {
                float2 w0 = *(const float2*)&Vs[s][nd*8 + gid][tig*2];
                bf[nd][0] = __float_as_uint(w0.x);
                bf[nd][1] = __float_as_uint(w0.y);
            }
            #pragma unroll
            for (int nd = 0; nd < 4; nd++)
                MMA_TF32(o[nd][0], o[nd][1], o[nd][2], o[nd][3],
                         af[0], af[1], af[2], af[3], bf[nd][0], bf[nd][1]);
        }
    }

    // write unnormalized partials + row stats
    int r0 = q0 + mb + gid, r1 = r0 + 8;
    size_t obase = (size_t)z * ROWS * DM;
    #pragma unroll
    for (int nd = 0; nd < 4; nd++) {
        int gd = h*DK + nd*8 + tig*2;
        g_part[obase + (size_t)(b*LL + r0)*DM + gd + 0] = o[nd][0];
        g_part[obase + (size_t)(b*LL + r0)*DM + gd + 1] = o[nd][1];
        g_part[obase + (size_t)(b*LL + r1)*DM + gd + 0] = o[nd][2];
        g_part[obase + (size_t)(b*LL + r1)*DM + gd + 1] = o[nd][3];
    }
    if (tig == 0) {
        g_fm[z*NBH*LL + bh*LL + r0] = m0;
        g_fl[z*NBH*LL + bh*LL + r0] = l0;
        g_fm[z*NBH*LL + bh*LL + r1] = m1;
        g_fl[z*NBH*LL + bh*LL + r1] = l1;
    }
}

// ---- combine the 2 KV splits: att = (a0*O0 + a1*O1) / (a0*l0 + a1*l1) ----
__global__ __launch_bounds__(256) void flash_combine()
{
    int idx = blockIdx.x * 256 + threadIdx.x;   // over ROWS*DM/4
    if (idx >= ROWS * (DM/4)) return;
    int gi = idx * 4;
    int gm = gi / DM;            // b*LL + q
    int col = gi % DM;
    int b = gm / LL, q = gm % LL;
    int h = col / DK;
    int bhq = (b*NH + h)*LL + q;
    float m0 = g_fm[bhq],          m1 = g_fm[NBH*LL + bhq];
    float l0 = g_fl[bhq],          l1 = g_fl[NBH*LL + bhq];
    float m  = fmaxf(m0, m1);
    float a0 = __expf(m0 - m), a1 = __expf(m1 - m);
    float inv = 1.f / (l0*a0 + l1*a1);
    float4 O0 = *(const float4*)&g_part[(size_t)gm*DM + col];
    float4 O1 = *(const float4*)&g_part[(size_t)(ROWS + gm)*DM + col];
    float4 r;
    r.x = (O0.x*a0 + O1.x*a1) * inv;
    r.y = (O0.y*a0 + O1.y*a1) * inv;
    r.z = (O0.z*a0 + O1.z*a1) * inv;
    r.w = (O0.w*a0 + O1.w*a1) * inv;
    *(float4*)&g_att[(size_t)gm*DM + col] = r;
}

// ---------------- host orchestration ----------------
extern "C" void kernel_launch(void* const* d_in, const int* in_sizes, int n_in,
                              void* d_out, int out_size)
{
    const float* x          = (const float*)d_in[0];
    const float* memory     = (const float*)d_in[1];
    // d_in[2] src_mask (all true), d_in[3] tgt_mask (unused)
    const float* in_proj_w  = (const float*)d_in[4];
    const float* conv_w     = (const float*)d_in[5];
    const float* conv_b     = (const float*)d_in[6];
    const float* x_proj_w   = (const float*)d_in[7];
    const float* dt_proj_w  = (const float*)d_in[8];
    const float* dt_proj_b  = (const float*)d_in[9];
    const float* A_log      = (const float*)d_in[10];
    const float* Dp         = (const float*)d_in[11];
    const float* out_proj_w = (const float*)d_in[12];
    const float* norm1_a    = (const float*)d_in[13];
    const float* norm1_b    = (const float*)d_in[14];
    const float* norm2_a    = (const float*)d_in[15];
    const float* norm2_b    = (const float*)d_in[16];
    const float* norm3_a    = (const float*)d_in[17];
    const float* norm3_b    = (const float*)d_in[18];
    const float* wq_w       = (const float*)d_in[19];
    const float* wq_b       = (const float*)d_in[20];
    const float* wk_w       = (const float*)d_in[21];
    const float* wk_b       = (const float*)d_in[22];
    const float* wv_w       = (const float*)d_in[23];
    const float* wv_b       = (const float*)d_in[24];
    const float* wo_w       = (const float*)d_in[25];
    const float* wo_b       = (const float*)d_in[26];
    const float* w1_w       = (const float*)d_in[27];
    const float* w1_b       = (const float*)d_in[28];
    const float* w2_w       = (const float*)d_in[29];
    const float* w2_b       = (const float*)d_in[30];
    float* out = (float*)d_out;

    float *p_ln, *p_xz, *p_u, *p_dbl, *p_dt, *p_yact, *p_h, *p_h2;
    float *p_q, *p_k, *p_v, *p_att, *p_ffh, *p_part;
    cudaGetSymbolAddress((void**)&p_ln,   g_ln);
    cudaGetSymbolAddress((void**)&p_xz,   g_xz);
    cudaGetSymbolAddress((void**)&p_u,    g_u);
    cudaGetSymbolAddress((void**)&p_dbl,  g_dbl);
    cudaGetSymbolAddress((void**)&p_dt,   g_dt);
    cudaGetSymbolAddress((void**)&p_yact, g_yact);
    cudaGetSymbolAddress((void**)&p_h,    g_h);
    cudaGetSymbolAddress((void**)&p_h2,   g_h2);
    cudaGetSymbolAddress((void**)&p_q,    g_q);
    cudaGetSymbolAddress((void**)&p_k,    g_k);
    cudaGetSymbolAddress((void**)&p_v,    g_v);
    cudaGetSymbolAddress((void**)&p_att,  g_att);
    cudaGetSymbolAddress((void**)&p_ffh,  g_ffh);
    cudaGetSymbolAddress((void**)&p_part, g_part);

    // ---- Mamba block ----
    ln_kernel<<<ROWS, DM>>>(x, norm1_a, norm1_b, p_ln);
    // xz = ln1 @ in_proj_w^T  (1024x2048x256): 64x64 -> 512 blocks
    launch_tgemm<64,64,32,2,2, 0,false,false,false>(p_ln, DM, in_proj_w, nullptr, nullptr, p_xz, XZW, ROWS, XZW, DM);
    // u = silu(causal_conv(xi))
    conv_silu_kernel<<<(ROWS*DI+255)/256, 256>>>(conv_w, conv_b);
    // dbl = u @ x_proj_w^T  (1024x272x1024): split-K8, 64x64 -> 640 blocks
    launch_tgemm<64,64,32,2,2, 0,false,false,true, 8,true>(p_u, DI, x_proj_w, nullptr, nullptr, p_part, XP_PAD, ROWS, DBLW, DI);
    reduceN_x<8><<<(ROWS*(DBLW/4)+255)/256, 256>>>();
    // dt = softplus(dbl[:, :16] @ dt_proj_w^T + b)  (1024x1024x16): 256 blocks
    launch_tgemm<64,64,16,2,2, 2,true,false,false>(p_dbl, DBLW, dt_proj_w, dt_proj_b, nullptr, p_dt, DI, ROWS, DI, DTR);
    // selective scan + (y + u*Dp)*silu(z)
    scan_kernel<<<(BB*DI)/8, 256>>>(A_log, Dp);
    // h = x + yact @ out_proj_w^T  (1024x256x1024): split-K2 -> 256 blocks, fused reduce+ln2
    launch_tgemm<64,32,32,4,1, 0,false,false,false, 2,true>(p_yact, DI, out_proj_w, nullptr, nullptr, p_part, DM, ROWS, DM, DI);
    reduce_ln<false><<<ROWS, DM>>>(nullptr, x, norm2_a, norm2_b, p_h, p_ln);

    // ---- Cross attention ----
    {
        QKVArgs qa;
        qa.A[0] = p_ln;   qa.W[0] = wq_w; qa.B[0] = wq_b; qa.C[0] = p_q;
        qa.A[1] = memory; qa.W[1] = wk_w; qa.B[1] = wk_b; qa.C[1] = p_k;
        qa.A[2] = memory; qa.W[2] = wv_w; qa.B[2] = wv_b; qa.C[2] = p_v;
        dim3 grid(DM/32, ROWS/64, 3);   // 384 blocks
        tgemm_qkv<<<grid, 128>>>(qa, DM, DM, ROWS, DM, DM);
    }
    {
        dim3 fgrid(LL/64, NBH, 2);      // 256 blocks, KV-split-2
        flash_attn<<<fgrid, 128>>>();
        flash_combine<<<(ROWS*(DM/4)+255)/256, 256>>>();
    }
    // h2 = h + att @ wo_w^T + wo_b: split-K2 -> 256 blocks, fused reduce+bias+ln3
    launch_tgemm<64,32,32,4,1, 0,false,false,false, 2,true>(p_att, DM, wo_w, nullptr, nullptr, p_part, DM, ROWS, DM, DM);
    reduce_ln<true><<<ROWS, DM>>>(wo_b, p_h, norm3_a, norm3_b, p_h2, p_ln);

    // ---- FFN ----
    // FF1 (1024x1024x256): 64x64 -> 256 blocks
    launch_tgemm<64,64,32,2,2, 1,true,false,false>(p_ln, DM, w1_w, w1_b, nullptr, p_ffh, DFF, ROWS, DFF, DM);
    // FF2 (1024x256x1024): split-K2 -> 256 blocks
    launch_tgemm<64,32,32,4,1, 0,false,false,false, 2,true>(p_ffh, DFF, w2_w, w2_b, nullptr, p_part, DM, ROWS, DM, DFF);
    reduce2_add<true><<<(ROWS*(DM/4)+255)/256, 256>>>(w2_b, p_h2, out);
}